// round 16
// baseline (speedup 1.0000x reference)
#include <cuda_runtime.h>
#include <cuda_fp16.h>
#include <math.h>
#include <stdint.h>

#define N_NODES 100000
#define E_EDGES 400000
#define ND 128
#define ED 64
#define HD 128
#define LN_EPS 1e-5f

// Scratch (__device__ globals: allocation-free rule)
__device__ __half g_hagg_h[(size_t)N_NODES * HD];  // fp16 atomic accumulator
__device__ float  g_deg[N_NODES];
__device__ __half g_PQh[(size_t)N_NODES * 256];    // [node][0:128]=P, [128:256]=Q
__device__ __half g_Rh[(size_t)E_EDGES * HD];      // ef@W1c + b1 (fp16)
__device__ float  g_d2[HD];

// Pre-split weight planes (hi/lo TF32). Flat layout:
//   w1 @ 0 (40960) [W1c rows at 32768] | uw1 @ 40960 (32768) |
//   uw2 @ 73728 (16384) | W2p @ 90112 (16384)
#define OFF_W1   0
#define OFF_W1C  32768
#define OFF_UW1  40960
#define OFF_UW2  73728
#define OFF_W2P  90112
#define N_SPLIT_IN 90112
__device__ float g_Whi[106496];
__device__ float g_Wlo[106496];

// ---------------- helpers ----------------
__device__ __forceinline__ void red_add_f32(float* p, float v) {
    asm volatile("red.global.add.f32 [%0], %1;" :: "l"(p), "f"(v) : "memory");
}
__device__ __forceinline__ void red_add_v4h(__half* p, uint32_t a, uint32_t b,
                                            uint32_t c, uint32_t d) {
    asm volatile("red.global.add.noftz.v4.f16x2 [%0], {%1, %2, %3, %4};"
                 :: "l"(p), "r"(a), "r"(b), "r"(c), "r"(d) : "memory");
}
__device__ __forceinline__ float2 split_f(float x) {
    uint32_t hi;
    asm("cvt.rna.tf32.f32 %0, %1;" : "=r"(hi) : "f"(x));
    float h = __uint_as_float(hi);
    float r = x - h;
    uint32_t lo;
    asm("cvt.rna.tf32.f32 %0, %1;" : "=r"(lo) : "f"(r));
    return make_float2(h, __uint_as_float(lo));
}
__device__ __forceinline__ uint32_t tf32_hi(float x) {
    uint32_t h;
    asm("cvt.rna.tf32.f32 %0, %1;" : "=r"(h) : "f"(x));
    return h;
}
__device__ __forceinline__ void mma_tf32(float d[4], const uint32_t a[4], const uint32_t b[2]) {
    asm("mma.sync.aligned.m16n8k8.row.col.f32.tf32.tf32.f32 "
        "{%0,%1,%2,%3}, {%4,%5,%6,%7}, {%8,%9}, {%0,%1,%2,%3};"
        : "+f"(d[0]), "+f"(d[1]), "+f"(d[2]), "+f"(d[3])
        : "r"(a[0]), "r"(a[1]), "r"(a[2]), "r"(a[3]), "r"(b[0]), "r"(b[1]));
}
__device__ __forceinline__ void cp_async16(void* smem, const void* gmem) {
    uint32_t s = (uint32_t)__cvta_generic_to_shared(smem);
    asm volatile("cp.async.cg.shared.global [%0], [%1], 16;" :: "r"(s), "l"(gmem));
}
__device__ __forceinline__ void cp_async8(void* smem, const void* gmem) {
    uint32_t s = (uint32_t)__cvta_generic_to_shared(smem);
    asm volatile("cp.async.ca.shared.global [%0], [%1], 8;" :: "r"(s), "l"(gmem));
}
#define CP_COMMIT() asm volatile("cp.async.commit_group;")
#define CP_WAIT1()  asm volatile("cp.async.wait_group 1;")

__device__ __forceinline__ float4 ld_half4(const __half* p) {
    uint2 u = *(const uint2*)p;
    __half2 a = *reinterpret_cast<__half2*>(&u.x);
    __half2 b = *reinterpret_cast<__half2*>(&u.y);
    float2 fa = __half22float2(a), fb = __half22float2(b);
    return make_float4(fa.x, fa.y, fb.x, fb.y);
}

__global__ void zero_kernel() {
    uint4* p = reinterpret_cast<uint4*>(g_hagg_h);
    const int n16 = (int)(((size_t)N_NODES * HD * 2) / 16);
    uint4 z = make_uint4(0, 0, 0, 0);
    for (int i = blockIdx.x * blockDim.x + threadIdx.x; i < n16;
         i += gridDim.x * blockDim.x)
        p[i] = z;
    for (int i = blockIdx.x * blockDim.x + threadIdx.x; i < N_NODES;
         i += gridDim.x * blockDim.x)
        g_deg[i] = 0.f;
}

__global__ void split_all_kernel(const float* __restrict__ w1,
                                 const float* __restrict__ uw1,
                                 const float* __restrict__ uw2)
{
    int i = blockIdx.x * blockDim.x + threadIdx.x;
    if (i >= N_SPLIT_IN) return;
    float v;
    if (i < OFF_UW1)       v = w1[i];
    else if (i < OFF_UW2)  v = uw1[i - OFF_UW1];
    else                   v = uw2[i - OFF_UW2];
    float2 s = split_f(v);
    g_Whi[i] = s.x;
    g_Wlo[i] = s.y;
}

// W2p = W2 @ uw1b (+split); block 128 computes d2 = b2 @ uw1b.
__global__ void w2p_kernel(const float* __restrict__ w2,
                           const float* __restrict__ uw1,
                           const float* __restrict__ b2) {
    int n = threadIdx.x;
    if (blockIdx.x == 128) {
        float s = 0.f;
        for (int k = 0; k < HD; k++)
            s = fmaf(b2[k], uw1[(ND + k) * HD + n], s);
        g_d2[n] = s;
        return;
    }
    int k = blockIdx.x;
    float s = 0.f;
    for (int m = 0; m < HD; m++)
        s = fmaf(w2[k * HD + m], uw1[(ND + m) * HD + n], s);
    float2 sp = split_f(s);
    g_Whi[OFF_W2P + k * HD + n] = sp.x;
    g_Wlo[OFF_W2P + k * HD + n] = sp.y;
}

// ---------------------------------------------------------------------------
// gemm_pq: P and Q in ONE pass (single-term TF32, fp16 output). Unchanged R15.
// ---------------------------------------------------------------------------
__global__ __launch_bounds__(256, 3) void gemm_pq(
    const float* __restrict__ nf, __half* __restrict__ PQ)
{
    extern __shared__ float sp[];
    #define AT(r, c)     sp[(r) * 132 + (c)]
    #define WPH(b, r, c) sp[8448 + (b) * 2176 + (r) * 136 + (c)]

    const int tid = threadIdx.x;
    const int lane = tid & 31, warp = tid >> 5;
    const int wm = warp >> 2, wn = warp & 3;
    const int g = lane >> 2, tig = lane & 3;
    const long rBase = (long)blockIdx.x * 64;

    const int arow = tid >> 2, akq = tid & 3;
    long gArow = rBase + arow; if (gArow >= N_NODES) gArow = N_NODES - 1;
    const int wkr = tid >> 5, wcc = tid & 31;

    #pragma unroll
    for (int j = 0; j < 8; j++)
        cp_async16(&AT(arow, j * 16 + akq * 4), nf + gArow * ND + j * 16 + akq * 4);
    {
        const float* Wh = g_Whi + OFF_W1;
        cp_async16(&WPH(0, wkr, wcc * 4),     Wh + (long)wkr * 128 + wcc * 4);
        cp_async16(&WPH(0, wkr + 8, wcc * 4), Wh + (long)(wkr + 8) * 128 + wcc * 4);
    }
    CP_COMMIT();

    float d[2][4][4];
    #pragma unroll
    for (int mf = 0; mf < 2; mf++)
        #pragma unroll
        for (int nf2 = 0; nf2 < 4; nf2++)
            #pragma unroll
            for (int q = 0; q < 4; q++) d[mf][nf2][q] = 0.f;

    for (int cg = 0; cg < 16; cg++) {
        if (cg + 1 < 16) {
            int buf = (cg + 1) & 1;
            int kc = ((cg + 1) & 7) * 16;
            const float* Wh = g_Whi + OFF_W1 + ((cg + 1) >> 3) * (ND * HD);
            cp_async16(&WPH(buf, wkr, wcc * 4),     Wh + (long)(kc + wkr) * 128 + wcc * 4);
            cp_async16(&WPH(buf, wkr + 8, wcc * 4), Wh + (long)(kc + 8 + wkr) * 128 + wcc * 4);
        }
        CP_COMMIT();
        CP_WAIT1();
        __syncthreads();
        const int buf = cg & 1;
        const int kc0 = (cg & 7) * 16;
        #pragma unroll
        for (int k8 = 0; k8 < 16; k8 += 8) {
            uint32_t ahi[2][4], bhi[4][2];
            #pragma unroll
            for (int mf = 0; mf < 2; mf++) {
                int mb = wm * 32 + mf * 16;
                ahi[mf][0] = tf32_hi(AT(mb + g,     kc0 + k8 + tig));
                ahi[mf][1] = tf32_hi(AT(mb + 8 + g, kc0 + k8 + tig));
                ahi[mf][2] = tf32_hi(AT(mb + g,     kc0 + k8 + tig + 4));
                ahi[mf][3] = tf32_hi(AT(mb + 8 + g, kc0 + k8 + tig + 4));
            }
            #pragma unroll
            for (int nf2 = 0; nf2 < 4; nf2++) {
                int nb = wn * 32 + nf2 * 8;
                bhi[nf2][0] = tf32_hi(WPH(buf, k8 + tig,     nb + g));
                bhi[nf2][1] = tf32_hi(WPH(buf, k8 + tig + 4, nb + g));
            }
            #pragma unroll
            for (int mf = 0; mf < 2; mf++)
                #pragma unroll
                for (int nf2 = 0; nf2 < 4; nf2++)
                    mma_tf32(d[mf][nf2], ahi[mf], bhi[nf2]);
        }
        __syncthreads();

        if ((cg & 7) == 7) {
            int colOff = (cg >> 3) * 128;
            #pragma unroll
            for (int mf = 0; mf < 2; mf++)
                #pragma unroll
                for (int r2 = 0; r2 < 2; r2++) {
                    long m = rBase + wm * 32 + mf * 16 + g + r2 * 8;
                    if (m < N_NODES) {
                        #pragma unroll
                        for (int nf2 = 0; nf2 < 4; nf2++) {
                            int n = wn * 32 + nf2 * 8 + 2 * tig;
                            *(__half2*)(PQ + m * 256 + colOff + n) =
                                __floats2half2_rn(d[mf][nf2][r2 * 2], d[mf][nf2][r2 * 2 + 1]);
                        }
                    }
                }
            #pragma unroll
            for (int mf = 0; mf < 2; mf++)
                #pragma unroll
                for (int nf2 = 0; nf2 < 4; nf2++)
                    #pragma unroll
                    for (int q = 0; q < 4; q++) d[mf][nf2][q] = 0.f;
        }
    }
    #undef AT
    #undef WPH
}

// ---------------------------------------------------------------------------
// msg_gemm: R = ef @ W1c + b1 -> g_Rh (fp16). Single-term TF32, K=64.
// ---------------------------------------------------------------------------
__global__ __launch_bounds__(256, 3) void msg_gemm(
    const float* __restrict__ ef, const float* __restrict__ b1)
{
    __shared__ float pool[6912];
    #define ASP(b, r, c)  pool[(b) * 1280 + (r) * 20 + (c)]
    #define WHSP(b, r, c) pool[2560 + (b) * 2176 + (r) * 136 + (c)]

    const float* Whi = g_Whi + OFF_W1C;

    const int tid = threadIdx.x;
    const int lane = tid & 31, warp = tid >> 5;
    const int wm = warp >> 2, wn = warp & 3;
    const int g = lane >> 2, tig = lane & 3;
    const long eBase = (long)blockIdx.x * 64;

    const int arow = tid >> 2, akq = tid & 3;
    const long gArow = eBase + arow;
    const int wkr = tid >> 5, wcc = tid & 31;

    float d[2][4][4];
    #pragma unroll
    for (int mf = 0; mf < 2; mf++)
        #pragma unroll
        for (int nf2 = 0; nf2 < 4; nf2++)
            #pragma unroll
            for (int q = 0; q < 4; q++) d[mf][nf2][q] = 0.f;

    cp_async16(&ASP(0, arow, akq * 4), ef + gArow * ED + akq * 4);
    cp_async16(&WHSP(0, wkr, wcc * 4),     Whi + (long)wkr * 128 + wcc * 4);
    cp_async16(&WHSP(0, wkr + 8, wcc * 4), Whi + (long)(wkr + 8) * 128 + wcc * 4);
    CP_COMMIT();

    for (int c = 0; c < 4; c++) {
        if (c + 1 < 4) {
            int kc = (c + 1) * 16, buf = (c + 1) & 1;
            cp_async16(&ASP(buf, arow, akq * 4), ef + gArow * ED + kc + akq * 4);
            cp_async16(&WHSP(buf, wkr, wcc * 4),     Whi + (long)(kc + wkr) * 128 + wcc * 4);
            cp_async16(&WHSP(buf, wkr + 8, wcc * 4), Whi + (long)(kc + 8 + wkr) * 128 + wcc * 4);
        }
        CP_COMMIT();
        CP_WAIT1();
        __syncthreads();
        const int buf = c & 1;
        #pragma unroll
        for (int k8 = 0; k8 < 16; k8 += 8) {
            uint32_t ahi[2][4], bhi[4][2];
            #pragma unroll
            for (int mf = 0; mf < 2; mf++) {
                int mb = wm * 32 + mf * 16;
                ahi[mf][0] = tf32_hi(ASP(buf, mb + g,     k8 + tig));
                ahi[mf][1] = tf32_hi(ASP(buf, mb + 8 + g, k8 + tig));
                ahi[mf][2] = tf32_hi(ASP(buf, mb + g,     k8 + tig + 4));
                ahi[mf][3] = tf32_hi(ASP(buf, mb + 8 + g, k8 + tig + 4));
            }
            #pragma unroll
            for (int nf2 = 0; nf2 < 4; nf2++) {
                int nb = wn * 32 + nf2 * 8;
                bhi[nf2][0] = tf32_hi(WHSP(buf, k8 + tig,     nb + g));
                bhi[nf2][1] = tf32_hi(WHSP(buf, k8 + tig + 4, nb + g));
            }
            #pragma unroll
            for (int mf = 0; mf < 2; mf++)
                #pragma unroll
                for (int nf2 = 0; nf2 < 4; nf2++)
                    mma_tf32(d[mf][nf2], ahi[mf], bhi[nf2]);
        }
        __syncthreads();
    }

    // epilogue: +b1, fp16 store
    #pragma unroll
    for (int mf = 0; mf < 2; mf++)
        #pragma unroll
        for (int r2 = 0; r2 < 2; r2++) {
            long row = eBase + wm * 32 + mf * 16 + g + r2 * 8;
            #pragma unroll
            for (int nf2 = 0; nf2 < 4; nf2++) {
                int n = wn * 32 + nf2 * 8 + 2 * tig;
                *(__half2*)(g_Rh + row * HD + n) =
                    __floats2half2_rn(d[mf][nf2][r2 * 2] + b1[n],
                                      d[mf][nf2][r2 * 2 + 1] + b1[n + 1]);
            }
        }
    #undef ASP
    #undef WHSP
}

// ---------------------------------------------------------------------------
// edge_kernel: one warp per UNDIRECTED edge (max parallelism, no SMEM).
//   fwd h=relu(LN(P[s]+Q[t]+R)) -> hagg[t]; bwd -> hagg[s]. v4.f16x2 scatter.
// ---------------------------------------------------------------------------
__global__ __launch_bounds__(256) void edge_kernel(
    const int* __restrict__ eidx,
    const float* __restrict__ g1, const float* __restrict__ be1)
{
    const int warp = threadIdx.x >> 5, lane = threadIdx.x & 31;
    const long e = (long)blockIdx.x * 8 + warp;
    const int s = eidx[e], t = eidx[E_EDGES + e];

    const __half* rowS = g_PQh + (size_t)s * 256;
    const __half* rowT = g_PQh + (size_t)t * 256;
    float4 ps = ld_half4(rowS + lane * 4);
    float4 qs = ld_half4(rowS + 128 + lane * 4);
    float4 pt = ld_half4(rowT + lane * 4);
    float4 qt = ld_half4(rowT + 128 + lane * 4);
    float4 r  = ld_half4(g_Rh + (size_t)e * HD + lane * 4);
    float4 gg = *(const float4*)&g1[lane * 4];
    float4 bb = *(const float4*)&be1[lane * 4];

    float4 vf = make_float4(ps.x + qt.x + r.x, ps.y + qt.y + r.y,
                            ps.z + qt.z + r.z, ps.w + qt.w + r.w);
    float4 vb = make_float4(pt.x + qs.x + r.x, pt.y + qs.y + r.y,
                            pt.z + qs.z + r.z, pt.w + qs.w + r.w);

    float s1f = vf.x + vf.y + vf.z + vf.w;
    float ssf = vf.x * vf.x + vf.y * vf.y + vf.z * vf.z + vf.w * vf.w;
    float s1b = vb.x + vb.y + vb.z + vb.w;
    float ssb = vb.x * vb.x + vb.y * vb.y + vb.z * vb.z + vb.w * vb.w;
    #pragma unroll
    for (int o = 16; o >= 1; o >>= 1) {
        s1f += __shfl_xor_sync(0xffffffffu, s1f, o);
        ssf += __shfl_xor_sync(0xffffffffu, ssf, o);
        s1b += __shfl_xor_sync(0xffffffffu, s1b, o);
        ssb += __shfl_xor_sync(0xffffffffu, ssb, o);
    }
    const bool evenLane = (lane & 1) == 0;
    {
        float mean = s1f * (1.0f / HD);
        float var  = ssf * (1.0f / HD) - mean * mean;
        float rstd = rsqrtf(var + LN_EPS);
        float h0 = fmaxf((vf.x - mean) * rstd * gg.x + bb.x, 0.f);
        float h1 = fmaxf((vf.y - mean) * rstd * gg.y + bb.y, 0.f);
        float h2 = fmaxf((vf.z - mean) * rstd * gg.z + bb.z, 0.f);
        float h3 = fmaxf((vf.w - mean) * rstd * gg.w + bb.w, 0.f);
        __half2 h01 = __floats2half2_rn(h0, h1);
        __half2 h23 = __floats2half2_rn(h2, h3);
        uint32_t u01 = *reinterpret_cast<uint32_t*>(&h01);
        uint32_t u23 = *reinterpret_cast<uint32_t*>(&h23);
        uint32_t p01 = __shfl_xor_sync(0xffffffffu, u01, 1);
        uint32_t p23 = __shfl_xor_sync(0xffffffffu, u23, 1);
        if (evenLane)
            red_add_v4h(g_hagg_h + (size_t)t * HD + lane * 4, u01, u23, p01, p23);
    }
    {
        float mean = s1b * (1.0f / HD);
        float var  = ssb * (1.0f / HD) - mean * mean;
        float rstd = rsqrtf(var + LN_EPS);
        float h0 = fmaxf((vb.x - mean) * rstd * gg.x + bb.x, 0.f);
        float h1 = fmaxf((vb.y - mean) * rstd * gg.y + bb.y, 0.f);
        float h2 = fmaxf((vb.z - mean) * rstd * gg.z + bb.z, 0.f);
        float h3 = fmaxf((vb.w - mean) * rstd * gg.w + bb.w, 0.f);
        __half2 h01 = __floats2half2_rn(h0, h1);
        __half2 h23 = __floats2half2_rn(h2, h3);
        uint32_t u01 = *reinterpret_cast<uint32_t*>(&h01);
        uint32_t u23 = *reinterpret_cast<uint32_t*>(&h23);
        uint32_t p01 = __shfl_xor_sync(0xffffffffu, u01, 1);
        uint32_t p23 = __shfl_xor_sync(0xffffffffu, u23, 1);
        if (evenLane)
            red_add_v4h(g_hagg_h + (size_t)s * HD + lane * 4, u01, u23, p01, p23);
    }
    if (lane == 0) { red_add_f32(g_deg + t, 1.0f); red_add_f32(g_deg + s, 1.0f); }
}

// ---------------------------------------------------------------------------
// upd_fused2: full update path in one kernel. Unchanged R15.
// ---------------------------------------------------------------------------
__global__ __launch_bounds__(256, 2) void upd_fused2(
    const float* __restrict__ nf, const float* __restrict__ ub1,
    const float* __restrict__ g2, const float* __restrict__ be2,
    const float* __restrict__ ub2, float* __restrict__ out)
{
    extern __shared__ float dpool[];
    #define WH2(b, r, c) dpool[(b) * 2176 + (r) * 136 + (c)]
    #define WL2(b, r, c) dpool[4352 + (b) * 2176 + (r) * 136 + (c)]
    #define ASF(b, r, c) dpool[8704 + (b) * 1280 + (r) * 20 + (c)]
    #define ASHP ((__half*)(dpool + 11264))
    #define ASH(b, r, c) ASHP[(b) * 1280 + (r) * 20 + (c)]
    #define CS2(r, c)    dpool[8704 + (r) * 132 + (c)]

    const int tid = threadIdx.x;
    const int lane = tid & 31, warp = tid >> 5;
    const int wm = warp >> 2, wn = warp & 3;
    const int g = lane >> 2, tig = lane & 3;
    const long rBase = (long)blockIdx.x * 64;

    const int arow = tid >> 2, akq = tid & 3;
    long gArow = rBase + arow; if (gArow >= N_NODES) gArow = N_NODES - 1;
    const int wkr = tid >> 5, wcc = tid & 31;

    float d[2][4][4];
    #pragma unroll
    for (int mf = 0; mf < 2; mf++)
        #pragma unroll
        for (int nf2 = 0; nf2 < 4; nf2++)
            #pragma unroll
            for (int q = 0; q < 4; q++) d[mf][nf2][q] = 0.f;

    {
        const float* Wh0 = g_Whi + OFF_UW1;
        const float* Wl0 = g_Wlo + OFF_UW1;
        cp_async16(&ASF(0, arow, akq * 4), nf + gArow * HD + akq * 4);
        cp_async16(&WH2(0, wkr, wcc * 4),     Wh0 + (long)wkr * 128 + wcc * 4);
        cp_async16(&WH2(0, wkr + 8, wcc * 4), Wh0 + (long)(wkr + 8) * 128 + wcc * 4);
        cp_async16(&WL2(0, wkr, wcc * 4),     Wl0 + (long)wkr * 128 + wcc * 4);
        cp_async16(&WL2(0, wkr + 8, wcc * 4), Wl0 + (long)(wkr + 8) * 128 + wcc * 4);
        CP_COMMIT();
    }

    for (int c = 0; c < 16; c++) {
        if (c + 1 < 16) {
            int cn = c + 1, buf = cn & 1;
            int kc = (cn & 7) * 16;
            const float* Whn = g_Whi + ((cn < 8) ? OFF_UW1 : OFF_W2P);
            const float* Wln = g_Wlo + ((cn < 8) ? OFF_UW1 : OFF_W2P);
            if (cn < 8)
                cp_async16(&ASF(buf, arow, akq * 4), nf + gArow * HD + kc + akq * 4);
            else
                cp_async8(&ASH(buf, arow, akq * 4), g_hagg_h + gArow * HD + kc + akq * 4);
            cp_async16(&WH2(buf, wkr, wcc * 4),     Whn + (long)(kc + wkr) * 128 + wcc * 4);
            cp_async16(&WH2(buf, wkr + 8, wcc * 4), Whn + (long)(kc + 8 + wkr) * 128 + wcc * 4);
            cp_async16(&WL2(buf, wkr, wcc * 4),     Wln + (long)(kc + wkr) * 128 + wcc * 4);
            cp_async16(&WL2(buf, wkr + 8, wcc * 4), Wln + (long)(kc + 8 + wkr) * 128 + wcc * 4);
        }
        CP_COMMIT();
        CP_WAIT1();
        __syncthreads();
        const int buf = c & 1;
        const bool fullPrec = (c < 8);
        #pragma unroll
        for (int k8 = 0; k8 < 16; k8 += 8) {
            uint32_t ahi[2][4], alo[2][4], bhi[4][2], blo[4][2];
            #pragma unroll
            for (int mf = 0; mf < 2; mf++) {
                int mb = wm * 32 + mf * 16;
                if (fullPrec) {
                    float2 s0 = split_f(ASF(buf, mb + g, k8 + tig));
                    float2 s1 = split_f(ASF(buf, mb + 8 + g, k8 + tig));
                    float2 s2 = split_f(ASF(buf, mb + g, k8 + tig + 4));
                    float2 s3 = split_f(ASF(buf, mb + 8 + g, k8 + tig + 4));
                    ahi[mf][0] = __float_as_uint(s0.x); alo[mf][0] = __float_as_uint(s0.y);
                    ahi[mf][1] = __float_as_uint(s1.x); alo[mf][1] = __float_as_uint(s1.y);
                    ahi[mf][2] = __float_as_uint(s2.x); alo[mf][2] = __float_as_uint(s2.y);
                    ahi[mf][3] = __float_as_uint(s3.x); alo[mf][3] = __float_as_uint(s3.y);
                } else {
                    ahi[mf][0] = tf32_hi(__half2float(ASH(buf, mb + g, k8 + tig)));
                    ahi[mf][1] = tf32_hi(__half2float(ASH(buf, mb + 8 + g, k8 + tig)));
                    ahi[mf][2] = tf32_hi(__half2float(ASH(buf, mb + g, k8 + tig + 4)));
                    ahi[mf][3] = tf32_hi(__half2float(ASH(buf, mb + 8 + g, k8 + tig + 4)));
                }
            }
            #pragma unroll
            for (int nf2 = 0; nf2 < 4; nf2++) {
                int nb = wn * 32 + nf2 * 8;
                bhi[nf2][0] = __float_as_uint(WH2(buf, k8 + tig, nb + g));
                bhi[nf2][1] = __float_as_uint(WH2(buf, k8 + tig + 4, nb + g));
                blo[nf2][0] = __float_as_uint(WL2(buf, k8 + tig, nb + g));
                blo[nf2][1] = __float_as_uint(WL2(buf, k8 + tig + 4, nb + g));
            }
            #pragma unroll
            for (int mf = 0; mf < 2; mf++)
                #pragma unroll
                for (int nf2 = 0; nf2 < 4; nf2++) {
                    mma_tf32(d[mf][nf2], ahi[mf], bhi[nf2]);
                    mma_tf32(d[mf][nf2], ahi[mf], blo[nf2]);
                    if (fullPrec) mma_tf32(d[mf][nf2], alo[mf], bhi[nf2]);
                }
        }
        __syncthreads();
    }

    #pragma unroll
    for (int mf = 0; mf < 2; mf++)
        #pragma unroll
        for (int r2 = 0; r2 < 2; r2++) {
            int lr = wm * 32 + mf * 16 + g + r2 * 8;
            #pragma unroll
            for (int nf2 = 0; nf2 < 4; nf2++) {
                int n = wn * 32 + nf2 * 8 + 2 * tig;
                CS2(lr, n)     = d[mf][nf2][r2 * 2];
                CS2(lr, n + 1) = d[mf][nf2][r2 * 2 + 1];
            }
        }
    __syncthreads();

    #pragma unroll
    for (int r8 = 0; r8 < 8; r8++) {
        int lr = warp * 8 + r8;
        long row = rBase + lr;
        long rowc = row < N_NODES ? row : N_NODES - 1;
        float dg = g_deg[rowc];
        int cc = lane * 4;
        float4 v = *(float4*)&CS2(lr, cc);
        float4 ub = *(const float4*)&ub1[cc];
        float4 dd = *(const float4*)&g_d2[cc];
        v.x += ub.x + dg * dd.x; v.y += ub.y + dg * dd.y;
        v.z += ub.z + dg * dd.z; v.w += ub.w + dg * dd.w;
        float s1 = v.x + v.y + v.z + v.w;
        float ss = v.x * v.x + v.y * v.y + v.z * v.z + v.w * v.w;
        #pragma unroll
        for (int o = 16; o >= 1; o >>= 1) {
            s1 += __shfl_xor_sync(0xffffffffu, s1, o);
            ss += __shfl_xor_sync(0xffffffffu, ss, o);
        }
        float mean = s1 * (1.0f / HD);
        float var  = ss * (1.0f / HD) - mean * mean;
        float rstd = rsqrtf(var + LN_EPS);
        float4 gg = *(const float4*)&g2[cc];
        float4 bb = *(const float4*)&be2[cc];
        float4 h;
        h.x = fmaxf((v.x - mean) * rstd * gg.x + bb.x, 0.f);
        h.y = fmaxf((v.y - mean) * rstd * gg.y + bb.y, 0.f);
        h.z = fmaxf((v.z - mean) * rstd * gg.z + bb.z, 0.f);
        h.w = fmaxf((v.w - mean) * rstd * gg.w + bb.w, 0.f);
        *(float4*)&CS2(lr, cc) = h;
    }
    __syncthreads();

    #pragma unroll
    for (int mf = 0; mf < 2; mf++)
        #pragma unroll
        for (int nf2 = 0; nf2 < 4; nf2++)
            #pragma unroll
            for (int q = 0; q < 4; q++) d[mf][nf2][q] = 0.f;
    {
        const float* Wh0 = g_Whi + OFF_UW2;
        const float* Wl0 = g_Wlo + OFF_UW2;
        cp_async16(&WH2(0, wkr, wcc * 4),     Wh0 + (long)wkr * 128 + wcc * 4);
        cp_async16(&WH2(0, wkr + 8, wcc * 4), Wh0 + (long)(wkr + 8) * 128 + wcc * 4);
        cp_async16(&WL2(0, wkr, wcc * 4),     Wl0 + (long)wkr * 128 + wcc * 4);
        cp_async16(&WL2(0, wkr + 8, wcc * 4), Wl0 + (long)(wkr + 8) * 128 + wcc * 4);
        CP_COMMIT();
    }
    for (int c = 0; c < 8; c++) {
        if (c + 1 < 8) {
            int kc = (c + 1) * 16, buf = (c + 1) & 1;
            const float* Whn = g_Whi + OFF_UW2;
            const float* Wln = g_Wlo + OFF_UW2;
            cp_async16(&WH2(buf, wkr, wcc * 4),     Whn + (long)(kc + wkr) * 128 + wcc * 4);
            cp_async16(&WH2(buf, wkr + 8, wcc * 4), Whn + (long)(kc + 8 + wkr) * 128 + wcc * 4);
            cp_async16(&WL2(buf, wkr, wcc * 4),     Wln + (long)(kc + wkr) * 128 + wcc * 4);
            cp_async16(&WL2(buf, wkr + 8, wcc * 4), Wln + (long)(kc + 8 + wkr) * 128 + wcc * 4);
        }
        CP_COMMIT();
        CP_WAIT1();
        __syncthreads();
        const int buf = c & 1;
        const int kc0 = c * 16;
        #pragma unroll
        for (int k8 = 0; k8 < 16; k8 += 8) {
            uint32_t ahi[2][4], alo[2][4], bhi[4][2], blo[4][2];
            #pragma unroll
            for (int mf = 0; mf < 2; mf++) {
                int mb = wm * 32 + mf * 16;
                float2 s0 = split_f(CS2(mb + g,     kc0 + k8 + tig));
                float2 s1 = split_f(CS2(mb + 8 + g, kc0 + k8 + tig));
                float2 s2 = split_f(CS2(mb + g,     kc0 + k8 + tig + 4));
                float2 s3 = split_f(CS2(mb + 8 + g, kc0 + k8 + tig + 4));
                ahi[mf][0] = __float_as_uint(s0.x); alo[mf][0] = __float_as_uint(s0.y);
                ahi[mf][1] = __float_as_uint(s1.x); alo[mf][1] = __float_as_uint(s1.y);
                ahi[mf][2] = __float_as_uint(s2.x); alo[mf][2] = __float_as_uint(s2.y);
                ahi[mf][3] = __float_as_uint(s3.x); alo[mf][3] = __float_as_uint(s3.y);
            }
            #pragma unroll
            for (int nf2 = 0; nf2 < 4; nf2++) {
                int nb = wn * 32 + nf2 * 8;
                bhi[nf2][0] = __float_as_uint(WH2(buf, k8 + tig, nb + g));
                bhi[nf2][1] = __float_as_uint(WH2(buf, k8 + tig + 4, nb + g));
                blo[nf2][0] = __float_as_uint(WL2(buf, k8 + tig, nb + g));
                blo[nf2][1] = __float_as_uint(WL2(buf, k8 + tig + 4, nb + g));
            }
            #pragma unroll
            for (int mf = 0; mf < 2; mf++)
                #pragma unroll
                for (int nf2 = 0; nf2 < 4; nf2++) {
                    mma_tf32(d[mf][nf2], ahi[mf], bhi[nf2]);
                    mma_tf32(d[mf][nf2], alo[mf], bhi[nf2]);
                    mma_tf32(d[mf][nf2], ahi[mf], blo[nf2]);
                }
        }
        __syncthreads();
    }

    #pragma unroll
    for (int mf = 0; mf < 2; mf++) {
        #pragma unroll
        for (int r2 = 0; r2 < 2; r2++) {
            long m = rBase + wm * 32 + mf * 16 + g + r2 * 8;
            if (m < N_NODES) {
                #pragma unroll
                for (int nf2 = 0; nf2 < 4; nf2++) {
                    int n = wn * 32 + nf2 * 8 + 2 * tig;
                    float2 rr = *(const float2*)(nf + m * 128 + n);
                    float v0 = d[mf][nf2][r2 * 2]     + ub2[n]     + rr.x;
                    float v1 = d[mf][nf2][r2 * 2 + 1] + ub2[n + 1] + rr.y;
                    *(float2*)(out + m * 128 + n) = make_float2(v0, v1);
                }
            }
        }
    }
}

extern "C" void kernel_launch(void* const* d_in, const int* in_sizes, int n_in,
                              void* d_out, int out_size)
{
    const float* nf   = (const float*)d_in[0];
    const float* ef   = (const float*)d_in[1];
    const int*   eidx = (const int*)  d_in[2];
    const float* w1   = (const float*)d_in[3];
    const float* b1   = (const float*)d_in[4];
    const float* g1   = (const float*)d_in[5];
    const float* be1  = (const float*)d_in[6];
    const float* w2   = (const float*)d_in[7];
    const float* b2   = (const float*)d_in[8];
    const float* uw1  = (const float*)d_in[9];
    const float* ub1  = (const float*)d_in[10];
    const float* g2   = (const float*)d_in[11];
    const float* be2  = (const float*)d_in[12];
    const float* uw2  = (const float*)d_in[13];
    const float* ub2  = (const float*)d_in[14];
    float* out = (float*)d_out;

    __half* dPQ;
    cudaGetSymbolAddress((void**)&dPQ, g_PQh);

    const int gN = (N_NODES + 63) / 64;   // 1563
    const int gE = E_EDGES / 64;          // 6250

    const int PQ_SMEM  = 12800 * 4;       // 51200 B
    const int UPD_SMEM = 17152 * 4;       // 68608 B
    cudaFuncSetAttribute(gemm_pq,   cudaFuncAttributeMaxDynamicSharedMemorySize, PQ_SMEM);
    cudaFuncSetAttribute(upd_fused2, cudaFuncAttributeMaxDynamicSharedMemorySize, UPD_SMEM);

    zero_kernel<<<592, 256>>>();
    split_all_kernel<<<(N_SPLIT_IN + 255) / 256, 256>>>(w1, uw1, uw2);
    w2p_kernel<<<129, 128>>>(w2, uw1, b2);
    // P and Q in one fused pass
    gemm_pq<<<gN, 256, PQ_SMEM>>>(nf, dPQ);
    // message: R-gemm (fp16 out) then max-parallelism edge phase
    msg_gemm<<<gE, 256>>>(ef, b1);
    edge_kernel<<<E_EDGES / 8, 256>>>(eidx, g1, be1);
    // fused update: GEMM1 + LN + GEMM2 + residual -> out
    upd_fused2<<<gN, 256, UPD_SMEM>>>(nf, ub1, g2, be2, ub2, out);
}

// round 17
// speedup vs baseline: 1.2441x; 1.2441x over previous
#include <cuda_runtime.h>
#include <cuda_fp16.h>
#include <math.h>
#include <stdint.h>

#define N_NODES 100000
#define E_EDGES 400000
#define ND 128
#define ED 64
#define HD 128
#define LN_EPS 1e-5f

// Scratch (__device__ globals: allocation-free rule)
__device__ __half g_hagg_h[(size_t)N_NODES * HD];  // fp16 atomic accumulator
__device__ float  g_deg[N_NODES];
__device__ __half g_PQh[(size_t)N_NODES * 256];    // [node][0:128]=P, [128:256]=Q
__device__ float  g_d2[HD];

// Pre-split weight planes (hi/lo TF32). Flat layout:
//   w1 @ 0 (40960) [W1c rows at 32768] | uw1 @ 40960 (32768) |
//   uw2 @ 73728 (16384) | W2p @ 90112 (16384)
#define OFF_W1   0
#define OFF_W1C  32768
#define OFF_UW1  40960
#define OFF_UW2  73728
#define OFF_W2P  90112
#define N_SPLIT_IN 90112
__device__ float g_Whi[106496];
__device__ float g_Wlo[106496];

// ---------------- helpers ----------------
__device__ __forceinline__ void red_add_f32(float* p, float v) {
    asm volatile("red.global.add.f32 [%0], %1;" :: "l"(p), "f"(v) : "memory");
}
__device__ __forceinline__ void red_add_v4h(__half* p, uint32_t a, uint32_t b,
                                            uint32_t c, uint32_t d) {
    asm volatile("red.global.add.noftz.v4.f16x2 [%0], {%1, %2, %3, %4};"
                 :: "l"(p), "r"(a), "r"(b), "r"(c), "r"(d) : "memory");
}
__device__ __forceinline__ float2 split_f(float x) {
    uint32_t hi;
    asm("cvt.rna.tf32.f32 %0, %1;" : "=r"(hi) : "f"(x));
    float h = __uint_as_float(hi);
    float r = x - h;
    uint32_t lo;
    asm("cvt.rna.tf32.f32 %0, %1;" : "=r"(lo) : "f"(r));
    return make_float2(h, __uint_as_float(lo));
}
__device__ __forceinline__ uint32_t tf32_hi(float x) {
    uint32_t h;
    asm("cvt.rna.tf32.f32 %0, %1;" : "=r"(h) : "f"(x));
    return h;
}
__device__ __forceinline__ void mma_tf32(float d[4], const uint32_t a[4], const uint32_t b[2]) {
    asm("mma.sync.aligned.m16n8k8.row.col.f32.tf32.tf32.f32 "
        "{%0,%1,%2,%3}, {%4,%5,%6,%7}, {%8,%9}, {%0,%1,%2,%3};"
        : "+f"(d[0]), "+f"(d[1]), "+f"(d[2]), "+f"(d[3])
        : "r"(a[0]), "r"(a[1]), "r"(a[2]), "r"(a[3]), "r"(b[0]), "r"(b[1]));
}
__device__ __forceinline__ void cp_async16(void* smem, const void* gmem) {
    uint32_t s = (uint32_t)__cvta_generic_to_shared(smem);
    asm volatile("cp.async.cg.shared.global [%0], [%1], 16;" :: "r"(s), "l"(gmem));
}
__device__ __forceinline__ void cp_async8(void* smem, const void* gmem) {
    uint32_t s = (uint32_t)__cvta_generic_to_shared(smem);
    asm volatile("cp.async.ca.shared.global [%0], [%1], 8;" :: "r"(s), "l"(gmem));
}
#define CP_COMMIT() asm volatile("cp.async.commit_group;")
#define CP_WAIT1()  asm volatile("cp.async.wait_group 1;")

__device__ __forceinline__ float4 ld_half4(const __half* p) {
    uint2 u = *(const uint2*)p;
    __half2 a = *reinterpret_cast<__half2*>(&u.x);
    __half2 b = *reinterpret_cast<__half2*>(&u.y);
    float2 fa = __half22float2(a), fb = __half22float2(b);
    return make_float4(fa.x, fa.y, fb.x, fb.y);
}

__global__ void zero_kernel() {
    uint4* p = reinterpret_cast<uint4*>(g_hagg_h);
    const int n16 = (int)(((size_t)N_NODES * HD * 2) / 16);
    uint4 z = make_uint4(0, 0, 0, 0);
    for (int i = blockIdx.x * blockDim.x + threadIdx.x; i < n16;
         i += gridDim.x * blockDim.x)
        p[i] = z;
    for (int i = blockIdx.x * blockDim.x + threadIdx.x; i < N_NODES;
         i += gridDim.x * blockDim.x)
        g_deg[i] = 0.f;
}

__global__ void split_all_kernel(const float* __restrict__ w1,
                                 const float* __restrict__ uw1,
                                 const float* __restrict__ uw2)
{
    int i = blockIdx.x * blockDim.x + threadIdx.x;
    if (i >= N_SPLIT_IN) return;
    float v;
    if (i < OFF_UW1)       v = w1[i];
    else if (i < OFF_UW2)  v = uw1[i - OFF_UW1];
    else                   v = uw2[i - OFF_UW2];
    float2 s = split_f(v);
    g_Whi[i] = s.x;
    g_Wlo[i] = s.y;
}

// W2p = W2 @ uw1b (+split); block 128 computes d2 = b2 @ uw1b.
__global__ void w2p_kernel(const float* __restrict__ w2,
                           const float* __restrict__ uw1,
                           const float* __restrict__ b2) {
    int n = threadIdx.x;
    if (blockIdx.x == 128) {
        float s = 0.f;
        for (int k = 0; k < HD; k++)
            s = fmaf(b2[k], uw1[(ND + k) * HD + n], s);
        g_d2[n] = s;
        return;
    }
    int k = blockIdx.x;
    float s = 0.f;
    for (int m = 0; m < HD; m++)
        s = fmaf(w2[k * HD + m], uw1[(ND + m) * HD + n], s);
    float2 sp = split_f(s);
    g_Whi[OFF_W2P + k * HD + n] = sp.x;
    g_Wlo[OFF_W2P + k * HD + n] = sp.y;
}

// ---------------------------------------------------------------------------
// gemm_pq: P and Q in ONE pass (single-term TF32, fp16 output). Unchanged R15.
// ---------------------------------------------------------------------------
__global__ __launch_bounds__(256, 3) void gemm_pq(
    const float* __restrict__ nf, __half* __restrict__ PQ)
{
    extern __shared__ float sp[];
    #define AT(r, c)     sp[(r) * 132 + (c)]
    #define WPH(b, r, c) sp[8448 + (b) * 2176 + (r) * 136 + (c)]

    const int tid = threadIdx.x;
    const int lane = tid & 31, warp = tid >> 5;
    const int wm = warp >> 2, wn = warp & 3;
    const int g = lane >> 2, tig = lane & 3;
    const long rBase = (long)blockIdx.x * 64;

    const int arow = tid >> 2, akq = tid & 3;
    long gArow = rBase + arow; if (gArow >= N_NODES) gArow = N_NODES - 1;
    const int wkr = tid >> 5, wcc = tid & 31;

    #pragma unroll
    for (int j = 0; j < 8; j++)
        cp_async16(&AT(arow, j * 16 + akq * 4), nf + gArow * ND + j * 16 + akq * 4);
    {
        const float* Wh = g_Whi + OFF_W1;
        cp_async16(&WPH(0, wkr, wcc * 4),     Wh + (long)wkr * 128 + wcc * 4);
        cp_async16(&WPH(0, wkr + 8, wcc * 4), Wh + (long)(wkr + 8) * 128 + wcc * 4);
    }
    CP_COMMIT();

    float d[2][4][4];
    #pragma unroll
    for (int mf = 0; mf < 2; mf++)
        #pragma unroll
        for (int nf2 = 0; nf2 < 4; nf2++)
            #pragma unroll
            for (int q = 0; q < 4; q++) d[mf][nf2][q] = 0.f;

    for (int cg = 0; cg < 16; cg++) {
        if (cg + 1 < 16) {
            int buf = (cg + 1) & 1;
            int kc = ((cg + 1) & 7) * 16;
            const float* Wh = g_Whi + OFF_W1 + ((cg + 1) >> 3) * (ND * HD);
            cp_async16(&WPH(buf, wkr, wcc * 4),     Wh + (long)(kc + wkr) * 128 + wcc * 4);
            cp_async16(&WPH(buf, wkr + 8, wcc * 4), Wh + (long)(kc + 8 + wkr) * 128 + wcc * 4);
        }
        CP_COMMIT();
        CP_WAIT1();
        __syncthreads();
        const int buf = cg & 1;
        const int kc0 = (cg & 7) * 16;
        #pragma unroll
        for (int k8 = 0; k8 < 16; k8 += 8) {
            uint32_t ahi[2][4], bhi[4][2];
            #pragma unroll
            for (int mf = 0; mf < 2; mf++) {
                int mb = wm * 32 + mf * 16;
                ahi[mf][0] = tf32_hi(AT(mb + g,     kc0 + k8 + tig));
                ahi[mf][1] = tf32_hi(AT(mb + 8 + g, kc0 + k8 + tig));
                ahi[mf][2] = tf32_hi(AT(mb + g,     kc0 + k8 + tig + 4));
                ahi[mf][3] = tf32_hi(AT(mb + 8 + g, kc0 + k8 + tig + 4));
            }
            #pragma unroll
            for (int nf2 = 0; nf2 < 4; nf2++) {
                int nb = wn * 32 + nf2 * 8;
                bhi[nf2][0] = tf32_hi(WPH(buf, k8 + tig,     nb + g));
                bhi[nf2][1] = tf32_hi(WPH(buf, k8 + tig + 4, nb + g));
            }
            #pragma unroll
            for (int mf = 0; mf < 2; mf++)
                #pragma unroll
                for (int nf2 = 0; nf2 < 4; nf2++)
                    mma_tf32(d[mf][nf2], ahi[mf], bhi[nf2]);
        }
        __syncthreads();

        if ((cg & 7) == 7) {
            int colOff = (cg >> 3) * 128;
            #pragma unroll
            for (int mf = 0; mf < 2; mf++)
                #pragma unroll
                for (int r2 = 0; r2 < 2; r2++) {
                    long m = rBase + wm * 32 + mf * 16 + g + r2 * 8;
                    if (m < N_NODES) {
                        #pragma unroll
                        for (int nf2 = 0; nf2 < 4; nf2++) {
                            int n = wn * 32 + nf2 * 8 + 2 * tig;
                            *(__half2*)(PQ + m * 256 + colOff + n) =
                                __floats2half2_rn(d[mf][nf2][r2 * 2], d[mf][nf2][r2 * 2 + 1]);
                        }
                    }
                }
            #pragma unroll
            for (int mf = 0; mf < 2; mf++)
                #pragma unroll
                for (int nf2 = 0; nf2 < 4; nf2++)
                    #pragma unroll
                    for (int q = 0; q < 4; q++) d[mf][nf2][q] = 0.f;
        }
    }
    #undef AT
    #undef WPH
}

// ---------------------------------------------------------------------------
// msg_fused (R15 config): per CTA 64 undirected edges. Single-term TF32
// R-gemm (K=64) -> SMEM; warp-per-edge LN; v4.f16x2 scatter. 3 CTAs/SM.
// ---------------------------------------------------------------------------
__global__ __launch_bounds__(256, 3) void msg_fused(
    const float* __restrict__ ef, const int* __restrict__ eidx,
    const float* __restrict__ b1,
    const float* __restrict__ g1, const float* __restrict__ be1)
{
    __shared__ float pool[8448];
    #define ASP(b, r, c)  pool[(b) * 1280 + (r) * 20 + (c)]
    #define WHSP(b, r, c) pool[2560 + (b) * 2176 + (r) * 136 + (c)]
    #define CSP(r, c)     pool[(r) * 132 + (c)]
    __shared__ int sS[64], sT[64];

    const float* Whi = g_Whi + OFF_W1C;

    const int tid = threadIdx.x;
    const int lane = tid & 31, warp = tid >> 5;
    const int wm = warp >> 2, wn = warp & 3;
    const int g = lane >> 2, tig = lane & 3;
    const long eBase = (long)blockIdx.x * 64;

    if (tid < 64) {
        sS[tid] = eidx[eBase + tid];
        sT[tid] = eidx[E_EDGES + eBase + tid];
    }

    const int arow = tid >> 2, akq = tid & 3;
    const long gArow = eBase + arow;
    const int wkr = tid >> 5, wcc = tid & 31;

    float d[2][4][4];
    #pragma unroll
    for (int mf = 0; mf < 2; mf++)
        #pragma unroll
        for (int nf2 = 0; nf2 < 4; nf2++)
            #pragma unroll
            for (int q = 0; q < 4; q++) d[mf][nf2][q] = 0.f;

    cp_async16(&ASP(0, arow, akq * 4), ef + gArow * ED + akq * 4);
    cp_async16(&WHSP(0, wkr, wcc * 4),     Whi + (long)wkr * 128 + wcc * 4);
    cp_async16(&WHSP(0, wkr + 8, wcc * 4), Whi + (long)(wkr + 8) * 128 + wcc * 4);
    CP_COMMIT();

    for (int c = 0; c < 4; c++) {
        if (c + 1 < 4) {
            int kc = (c + 1) * 16, buf = (c + 1) & 1;
            cp_async16(&ASP(buf, arow, akq * 4), ef + gArow * ED + kc + akq * 4);
            cp_async16(&WHSP(buf, wkr, wcc * 4),     Whi + (long)(kc + wkr) * 128 + wcc * 4);
            cp_async16(&WHSP(buf, wkr + 8, wcc * 4), Whi + (long)(kc + 8 + wkr) * 128 + wcc * 4);
        }
        CP_COMMIT();
        CP_WAIT1();
        __syncthreads();
        const int buf = c & 1;
        #pragma unroll
        for (int k8 = 0; k8 < 16; k8 += 8) {
            uint32_t ahi[2][4], bhi[4][2];
            #pragma unroll
            for (int mf = 0; mf < 2; mf++) {
                int mb = wm * 32 + mf * 16;
                ahi[mf][0] = tf32_hi(ASP(buf, mb + g,     k8 + tig));
                ahi[mf][1] = tf32_hi(ASP(buf, mb + 8 + g, k8 + tig));
                ahi[mf][2] = tf32_hi(ASP(buf, mb + g,     k8 + tig + 4));
                ahi[mf][3] = tf32_hi(ASP(buf, mb + 8 + g, k8 + tig + 4));
            }
            #pragma unroll
            for (int nf2 = 0; nf2 < 4; nf2++) {
                int nb = wn * 32 + nf2 * 8;
                bhi[nf2][0] = tf32_hi(WHSP(buf, k8 + tig,     nb + g));
                bhi[nf2][1] = tf32_hi(WHSP(buf, k8 + tig + 4, nb + g));
            }
            #pragma unroll
            for (int mf = 0; mf < 2; mf++)
                #pragma unroll
                for (int nf2 = 0; nf2 < 4; nf2++)
                    mma_tf32(d[mf][nf2], ahi[mf], bhi[nf2]);
        }
        __syncthreads();
    }

    #pragma unroll
    for (int mf = 0; mf < 2; mf++)
        #pragma unroll
        for (int r2 = 0; r2 < 2; r2++) {
            int lr = wm * 32 + mf * 16 + g + r2 * 8;
            #pragma unroll
            for (int nf2 = 0; nf2 < 4; nf2++) {
                int n = wn * 32 + nf2 * 8 + 2 * tig;
                CSP(lr, n)     = d[mf][nf2][r2 * 2]     + b1[n];
                CSP(lr, n + 1) = d[mf][nf2][r2 * 2 + 1] + b1[n + 1];
            }
        }
    __syncthreads();

    float4 gg = *(const float4*)&g1[lane * 4];
    float4 bb = *(const float4*)&be1[lane * 4];
    const bool evenLane = (lane & 1) == 0;
    #pragma unroll 2
    for (int r8 = 0; r8 < 8; r8++) {
        int lr = warp * 8 + r8;
        int s = sS[lr], t = sT[lr];
        const __half* rowS = g_PQh + (size_t)s * 256;
        const __half* rowT = g_PQh + (size_t)t * 256;
        float4 ps = ld_half4(rowS + lane * 4);
        float4 qs = ld_half4(rowS + 128 + lane * 4);
        float4 pt = ld_half4(rowT + lane * 4);
        float4 qt = ld_half4(rowT + 128 + lane * 4);
        float4 r  = *(float4*)&CSP(lr, lane * 4);

        float4 vf = make_float4(ps.x + qt.x + r.x, ps.y + qt.y + r.y,
                                ps.z + qt.z + r.z, ps.w + qt.w + r.w);
        float4 vb = make_float4(pt.x + qs.x + r.x, pt.y + qs.y + r.y,
                                pt.z + qs.z + r.z, pt.w + qs.w + r.w);

        float s1f = vf.x + vf.y + vf.z + vf.w;
        float ssf = vf.x * vf.x + vf.y * vf.y + vf.z * vf.z + vf.w * vf.w;
        float s1b = vb.x + vb.y + vb.z + vb.w;
        float ssb = vb.x * vb.x + vb.y * vb.y + vb.z * vb.z + vb.w * vb.w;
        #pragma unroll
        for (int o = 16; o >= 1; o >>= 1) {
            s1f += __shfl_xor_sync(0xffffffffu, s1f, o);
            ssf += __shfl_xor_sync(0xffffffffu, ssf, o);
            s1b += __shfl_xor_sync(0xffffffffu, s1b, o);
            ssb += __shfl_xor_sync(0xffffffffu, ssb, o);
        }
        {
            float mean = s1f * (1.0f / HD);
            float var  = ssf * (1.0f / HD) - mean * mean;
            float rstd = rsqrtf(var + LN_EPS);
            float h0 = fmaxf((vf.x - mean) * rstd * gg.x + bb.x, 0.f);
            float h1 = fmaxf((vf.y - mean) * rstd * gg.y + bb.y, 0.f);
            float h2 = fmaxf((vf.z - mean) * rstd * gg.z + bb.z, 0.f);
            float h3 = fmaxf((vf.w - mean) * rstd * gg.w + bb.w, 0.f);
            __half2 h01 = __floats2half2_rn(h0, h1);
            __half2 h23 = __floats2half2_rn(h2, h3);
            uint32_t u01 = *reinterpret_cast<uint32_t*>(&h01);
            uint32_t u23 = *reinterpret_cast<uint32_t*>(&h23);
            uint32_t p01 = __shfl_xor_sync(0xffffffffu, u01, 1);
            uint32_t p23 = __shfl_xor_sync(0xffffffffu, u23, 1);
            if (evenLane)
                red_add_v4h(g_hagg_h + (size_t)t * HD + lane * 4, u01, u23, p01, p23);
        }
        {
            float mean = s1b * (1.0f / HD);
            float var  = ssb * (1.0f / HD) - mean * mean;
            float rstd = rsqrtf(var + LN_EPS);
            float h0 = fmaxf((vb.x - mean) * rstd * gg.x + bb.x, 0.f);
            float h1 = fmaxf((vb.y - mean) * rstd * gg.y + bb.y, 0.f);
            float h2 = fmaxf((vb.z - mean) * rstd * gg.z + bb.z, 0.f);
            float h3 = fmaxf((vb.w - mean) * rstd * gg.w + bb.w, 0.f);
            __half2 h01 = __floats2half2_rn(h0, h1);
            __half2 h23 = __floats2half2_rn(h2, h3);
            uint32_t u01 = *reinterpret_cast<uint32_t*>(&h01);
            uint32_t u23 = *reinterpret_cast<uint32_t*>(&h23);
            uint32_t p01 = __shfl_xor_sync(0xffffffffu, u01, 1);
            uint32_t p23 = __shfl_xor_sync(0xffffffffu, u23, 1);
            if (evenLane)
                red_add_v4h(g_hagg_h + (size_t)s * HD + lane * 4, u01, u23, p01, p23);
        }
        if (lane == 0) { red_add_f32(g_deg + t, 1.0f); red_add_f32(g_deg + s, 1.0f); }
    }
    #undef ASP
    #undef WHSP
    #undef CSP
}

// ---------------------------------------------------------------------------
// upd_fused3: full update path, SINGLE-term TF32 both mainloops (no lo planes).
//   T = nf@uw1a + hagg@W2p; H = relu(LN(T+ub1+deg*d2)); out = H@uw2+ub2+nf
// SMEM (floats): WH[2][16][136] @0 (4352); A/C region @4352:
//   ASF[2][64][20] @4352 (2560); ASH (half) @6912 (1280); CS2[64][132] @4352.
// Total 12800 floats = 51200 B -> 3 CTAs/SM.
// ---------------------------------------------------------------------------
__global__ __launch_bounds__(256, 3) void upd_fused3(
    const float* __restrict__ nf, const float* __restrict__ ub1,
    const float* __restrict__ g2, const float* __restrict__ be2,
    const float* __restrict__ ub2, float* __restrict__ out)
{
    extern __shared__ float dpool[];
    #define WH2(b, r, c) dpool[(b) * 2176 + (r) * 136 + (c)]
    #define ASF(b, r, c) dpool[4352 + (b) * 1280 + (r) * 20 + (c)]
    #define ASHP ((__half*)(dpool + 6912))
    #define ASH(b, r, c) ASHP[(b) * 1280 + (r) * 20 + (c)]
    #define CS2(r, c)    dpool[4352 + (r) * 132 + (c)]

    const int tid = threadIdx.x;
    const int lane = tid & 31, warp = tid >> 5;
    const int wm = warp >> 2, wn = warp & 3;
    const int g = lane >> 2, tig = lane & 3;
    const long rBase = (long)blockIdx.x * 64;

    const int arow = tid >> 2, akq = tid & 3;
    long gArow = rBase + arow; if (gArow >= N_NODES) gArow = N_NODES - 1;
    const int wkr = tid >> 5, wcc = tid & 31;

    float d[2][4][4];
    #pragma unroll
    for (int mf = 0; mf < 2; mf++)
        #pragma unroll
        for (int nf2 = 0; nf2 < 4; nf2++)
            #pragma unroll
            for (int q = 0; q < 4; q++) d[mf][nf2][q] = 0.f;

    {
        const float* Wh0 = g_Whi + OFF_UW1;
        cp_async16(&ASF(0, arow, akq * 4), nf + gArow * HD + akq * 4);
        cp_async16(&WH2(0, wkr, wcc * 4),     Wh0 + (long)wkr * 128 + wcc * 4);
        cp_async16(&WH2(0, wkr + 8, wcc * 4), Wh0 + (long)(wkr + 8) * 128 + wcc * 4);
        CP_COMMIT();
    }

    for (int c = 0; c < 16; c++) {
        if (c + 1 < 16) {
            int cn = c + 1, buf = cn & 1;
            int kc = (cn & 7) * 16;
            const float* Whn = g_Whi + ((cn < 8) ? OFF_UW1 : OFF_W2P);
            if (cn < 8)
                cp_async16(&ASF(buf, arow, akq * 4), nf + gArow * HD + kc + akq * 4);
            else
                cp_async8(&ASH(buf, arow, akq * 4), g_hagg_h + gArow * HD + kc + akq * 4);
            cp_async16(&WH2(buf, wkr, wcc * 4),     Whn + (long)(kc + wkr) * 128 + wcc * 4);
            cp_async16(&WH2(buf, wkr + 8, wcc * 4), Whn + (long)(kc + 8 + wkr) * 128 + wcc * 4);
        }
        CP_COMMIT();
        CP_WAIT1();
        __syncthreads();
        const int buf = c & 1;
        const bool fromF = (c < 8);
        #pragma unroll
        for (int k8 = 0; k8 < 16; k8 += 8) {
            uint32_t ahi[2][4], bhi[4][2];
            #pragma unroll
            for (int mf = 0; mf < 2; mf++) {
                int mb = wm * 32 + mf * 16;
                if (fromF) {
                    ahi[mf][0] = tf32_hi(ASF(buf, mb + g, k8 + tig));
                    ahi[mf][1] = tf32_hi(ASF(buf, mb + 8 + g, k8 + tig));
                    ahi[mf][2] = tf32_hi(ASF(buf, mb + g, k8 + tig + 4));
                    ahi[mf][3] = tf32_hi(ASF(buf, mb + 8 + g, k8 + tig + 4));
                } else {
                    ahi[mf][0] = tf32_hi(__half2float(ASH(buf, mb + g, k8 + tig)));
                    ahi[mf][1] = tf32_hi(__half2float(ASH(buf, mb + 8 + g, k8 + tig)));
                    ahi[mf][2] = tf32_hi(__half2float(ASH(buf, mb + g, k8 + tig + 4)));
                    ahi[mf][3] = tf32_hi(__half2float(ASH(buf, mb + 8 + g, k8 + tig + 4)));
                }
            }
            #pragma unroll
            for (int nf2 = 0; nf2 < 4; nf2++) {
                int nb = wn * 32 + nf2 * 8;
                bhi[nf2][0] = __float_as_uint(WH2(buf, k8 + tig, nb + g));
                bhi[nf2][1] = __float_as_uint(WH2(buf, k8 + tig + 4, nb + g));
            }
            #pragma unroll
            for (int mf = 0; mf < 2; mf++)
                #pragma unroll
                for (int nf2 = 0; nf2 < 4; nf2++)
                    mma_tf32(d[mf][nf2], ahi[mf], bhi[nf2]);
        }
        __syncthreads();
    }

    // stage T -> CS2
    #pragma unroll
    for (int mf = 0; mf < 2; mf++)
        #pragma unroll
        for (int r2 = 0; r2 < 2; r2++) {
            int lr = wm * 32 + mf * 16 + g + r2 * 8;
            #pragma unroll
            for (int nf2 = 0; nf2 < 4; nf2++) {
                int n = wn * 32 + nf2 * 8 + 2 * tig;
                CS2(lr, n)     = d[mf][nf2][r2 * 2];
                CS2(lr, n + 1) = d[mf][nf2][r2 * 2 + 1];
            }
        }
    __syncthreads();

    // LN(+ub1+deg*d2) -> relu -> H back into CS2
    #pragma unroll
    for (int r8 = 0; r8 < 8; r8++) {
        int lr = warp * 8 + r8;
        long row = rBase + lr;
        long rowc = row < N_NODES ? row : N_NODES - 1;
        float dg = g_deg[rowc];
        int cc = lane * 4;
        float4 v = *(float4*)&CS2(lr, cc);
        float4 ub = *(const float4*)&ub1[cc];
        float4 dd = *(const float4*)&g_d2[cc];
        v.x += ub.x + dg * dd.x; v.y += ub.y + dg * dd.y;
        v.z += ub.z + dg * dd.z; v.w += ub.w + dg * dd.w;
        float s1 = v.x + v.y + v.z + v.w;
        float ss = v.x * v.x + v.y * v.y + v.z * v.z + v.w * v.w;
        #pragma unroll
        for (int o = 16; o >= 1; o >>= 1) {
            s1 += __shfl_xor_sync(0xffffffffu, s1, o);
            ss += __shfl_xor_sync(0xffffffffu, ss, o);
        }
        float mean = s1 * (1.0f / HD);
        float var  = ss * (1.0f / HD) - mean * mean;
        float rstd = rsqrtf(var + LN_EPS);
        float4 gg = *(const float4*)&g2[cc];
        float4 bb = *(const float4*)&be2[cc];
        float4 h;
        h.x = fmaxf((v.x - mean) * rstd * gg.x + bb.x, 0.f);
        h.y = fmaxf((v.y - mean) * rstd * gg.y + bb.y, 0.f);
        h.z = fmaxf((v.z - mean) * rstd * gg.z + bb.z, 0.f);
        h.w = fmaxf((v.w - mean) * rstd * gg.w + bb.w, 0.f);
        *(float4*)&CS2(lr, cc) = h;
    }
    __syncthreads();

    // mainloop2: out-tile = H(CS2) @ uw2 (single-term)
    #pragma unroll
    for (int mf = 0; mf < 2; mf++)
        #pragma unroll
        for (int nf2 = 0; nf2 < 4; nf2++)
            #pragma unroll
            for (int q = 0; q < 4; q++) d[mf][nf2][q] = 0.f;
    // W buffers are in WH region (disjoint from CS2 @4352+) — safe to stream.
    {
        const float* Wh0 = g_Whi + OFF_UW2;
        cp_async16(&WH2(0, wkr, wcc * 4),     Wh0 + (long)wkr * 128 + wcc * 4);
        cp_async16(&WH2(0, wkr + 8, wcc * 4), Wh0 + (long)(wkr + 8) * 128 + wcc * 4);
        CP_COMMIT();
    }
    for (int c = 0; c < 8; c++) {
        if (c + 1 < 8) {
            int kc = (c + 1) * 16, buf = (c + 1) & 1;
            const float* Whn = g_Whi + OFF_UW2;
            cp_async16(&WH2(buf, wkr, wcc * 4),     Whn + (long)(kc + wkr) * 128 + wcc * 4);
            cp_async16(&WH2(buf, wkr + 8, wcc * 4), Whn + (long)(kc + 8 + wkr) * 128 + wcc * 4);
        }
        CP_COMMIT();
        CP_WAIT1();
        __syncthreads();
        const int buf = c & 1;
        const int kc0 = c * 16;
        #pragma unroll
        for (int k8 = 0; k8 < 16; k8 += 8) {
            uint32_t ahi[2][4], bhi[4][2];
            #pragma unroll
            for (int mf = 0; mf < 2; mf++) {
                int mb = wm * 32 + mf * 16;
                ahi[mf][0] = tf32_hi(CS2(mb + g,     kc0 + k8 + tig));
                ahi[mf][1] = tf32_hi(CS2(mb + 8 + g, kc0 + k8 + tig));
                ahi[mf][2] = tf32_hi(CS2(mb + g,     kc0 + k8 + tig + 4));
                ahi[mf][3] = tf32_hi(CS2(mb + 8 + g, kc0 + k8 + tig + 4));
            }
            #pragma unroll
            for (int nf2 = 0; nf2 < 4; nf2++) {
                int nb = wn * 32 + nf2 * 8;
                bhi[nf2][0] = __float_as_uint(WH2(buf, k8 + tig, nb + g));
                bhi[nf2][1] = __float_as_uint(WH2(buf, k8 + tig + 4, nb + g));
            }
            #pragma unroll
            for (int mf = 0; mf < 2; mf++)
                #pragma unroll
                for (int nf2 = 0; nf2 < 4; nf2++)
                    mma_tf32(d[mf][nf2], ahi[mf], bhi[nf2]);
        }
        __syncthreads();
    }

    // epilogue: out = d + ub2 + nf
    #pragma unroll
    for (int mf = 0; mf < 2; mf++) {
        #pragma unroll
        for (int r2 = 0; r2 < 2; r2++) {
            long m = rBase + wm * 32 + mf * 16 + g + r2 * 8;
            if (m < N_NODES) {
                #pragma unroll
                for (int nf2 = 0; nf2 < 4; nf2++) {
                    int n = wn * 32 + nf2 * 8 + 2 * tig;
                    float2 rr = *(const float2*)(nf + m * 128 + n);
                    float v0 = d[mf][nf2][r2 * 2]     + ub2[n]     + rr.x;
                    float v1 = d[mf][nf2][r2 * 2 + 1] + ub2[n + 1] + rr.y;
                    *(float2*)(out + m * 128 + n) = make_float2(v0, v1);
                }
            }
        }
    }
}

extern "C" void kernel_launch(void* const* d_in, const int* in_sizes, int n_in,
                              void* d_out, int out_size)
{
    const float* nf   = (const float*)d_in[0];
    const float* ef   = (const float*)d_in[1];
    const int*   eidx = (const int*)  d_in[2];
    const float* w1   = (const float*)d_in[3];
    const float* b1   = (const float*)d_in[4];
    const float* g1   = (const float*)d_in[5];
    const float* be1  = (const float*)d_in[6];
    const float* w2   = (const float*)d_in[7];
    const float* b2   = (const float*)d_in[8];
    const float* uw1  = (const float*)d_in[9];
    const float* ub1  = (const float*)d_in[10];
    const float* g2   = (const float*)d_in[11];
    const float* be2  = (const float*)d_in[12];
    const float* uw2  = (const float*)d_in[13];
    const float* ub2  = (const float*)d_in[14];
    float* out = (float*)d_out;

    __half* dPQ;
    cudaGetSymbolAddress((void**)&dPQ, g_PQh);

    const int gN = (N_NODES + 63) / 64;   // 1563
    const int gE = E_EDGES / 64;          // 6250

    const int PQ_SMEM  = 12800 * 4;       // 51200 B
    const int UPD_SMEM = 12800 * 4;       // 51200 B
    cudaFuncSetAttribute(gemm_pq,   cudaFuncAttributeMaxDynamicSharedMemorySize, PQ_SMEM);
    cudaFuncSetAttribute(upd_fused3, cudaFuncAttributeMaxDynamicSharedMemorySize, UPD_SMEM);

    zero_kernel<<<592, 256>>>();
    split_all_kernel<<<(N_SPLIT_IN + 255) / 256, 256>>>(w1, uw1, uw2);
    w2p_kernel<<<129, 128>>>(w2, uw1, b2);
    // P and Q in one fused pass
    gemm_pq<<<gN, 256, PQ_SMEM>>>(nf, dPQ);
    // fused message: R-gemm + gather + LN + v4.f16x2 scatter
    msg_fused<<<gE, 256>>>(ef, eidx, b1, g1, be1);
    // fused update: GEMM1 + LN + GEMM2 + residual -> out (single-term TF32)
    upd_fused3<<<gN, 256, UPD_SMEM>>>(nf, ub1, g2, be2, ub2, out);
}